// round 11
// baseline (speedup 1.0000x reference)
#include <cuda_runtime.h>
#include <cuda_bf16.h>
#include <cstdint>

#define DIMS 512
#define K2   1536    // split-expanded K (3 * DIMS)
#define SEQL 2048
#define NBATCH 2
#define EMAX 2458
#define CMAX 1844
#define SLD  2464   // padded score row stride
#define NV   32000

// ---------------- device scratch (static: no allocs allowed) ----------------
__device__ float g_s_state[NBATCH][SEQL][DIMS];
__device__ float g_s_val  [NBATCH][SEQL][DIMS];
__device__ float g_e_state[NBATCH][EMAX][DIMS];
__device__ float g_e_val  [NBATCH][EMAX][DIMS];
__device__ float g_c_state[NBATCH][CMAX][DIMS];
__device__ float g_c_val  [NBATCH][CMAX][DIMS];
__device__ float g_tmp_state[NBATCH][EMAX][DIMS];
__device__ float g_tmp_val  [NBATCH][EMAX][DIMS];
__device__ float g_scores[NBATCH][EMAX * SLD];
// split-bf16 expanded operands
__device__ __nv_bfloat16 g_A2[(size_t)NBATCH * EMAX * K2];   // A side: [hi, hi, lo]
__device__ __nv_bfloat16 g_B2[(size_t)NBATCH * EMAX * K2];   // B side: [hi, lo, hi]
__device__ __nv_bfloat16 g_W2[(size_t)NV * K2];              // readout W^T split: [hi, lo, hi]

__device__ __forceinline__ float* arr_state(int w, int b) {
    if (w == 0) return &g_s_state[b][0][0];
    if (w == 1) return &g_e_state[b][0][0];
    if (w == 2) return &g_c_state[b][0][0];
    return &g_tmp_state[b][0][0];
}
__device__ __forceinline__ float* arr_val(int w, int b) {
    if (w == 0) return &g_s_val[b][0][0];
    if (w == 1) return &g_e_val[b][0][0];
    if (w == 2) return &g_c_val[b][0][0];
    return &g_tmp_val[b][0][0];
}

__device__ __forceinline__ uint32_t smem_u32(const void* p) {
    uint32_t a;
    asm("{ .reg .u64 t; cvta.to.shared.u64 t, %1; cvt.u32.u64 %0, t; }" : "=r"(a) : "l"(p));
    return a;
}
__device__ __forceinline__ void ldm_x4(uint32_t* r, uint32_t addr) {
    asm volatile("ldmatrix.sync.aligned.m8n8.x4.shared.b16 {%0,%1,%2,%3}, [%4];"
                 : "=r"(r[0]), "=r"(r[1]), "=r"(r[2]), "=r"(r[3]) : "r"(addr));
}
__device__ __forceinline__ void ldm_x2(uint32_t* r, uint32_t addr) {
    asm volatile("ldmatrix.sync.aligned.m8n8.x2.shared.b16 {%0,%1}, [%2];"
                 : "=r"(r[0]), "=r"(r[1]) : "r"(addr));
}
__device__ __forceinline__ void mma_bf16(float* c, const uint32_t* a, const uint32_t* b) {
    asm volatile("mma.sync.aligned.m16n8k16.row.col.f32.bf16.bf16.f32 "
                 "{%0,%1,%2,%3}, {%4,%5,%6,%7}, {%8,%9}, {%0,%1,%2,%3};"
                 : "+f"(c[0]), "+f"(c[1]), "+f"(c[2]), "+f"(c[3])
                 : "r"(a[0]), "r"(a[1]), "r"(a[2]), "r"(a[3]), "r"(b[0]), "r"(b[1]));
}
__device__ __forceinline__ void cp16(uint32_t saddr, const void* gaddr) {
    asm volatile("cp.async.cg.shared.global [%0], [%1], 16;" :: "r"(saddr), "l"(gaddr));
}
#define CP_COMMIT() asm volatile("cp.async.commit_group;" ::: "memory")
#define CP_WAIT0()  asm volatile("cp.async.wait_group 0;" ::: "memory")
#define CP_WAIT1()  asm volatile("cp.async.wait_group 1;" ::: "memory")

// ---------------- init kernels ----------------
__global__ void k_embed_init(const int* __restrict__ tokens, const float* __restrict__ embed) {
    int b = blockIdx.y, s = blockIdx.x, t = threadIdx.x;
    int tok = tokens[b * SEQL + s];
    float4 v = ((const float4*)(embed + (long long)tok * DIMS))[t];
    ((float4*)g_s_state[b][s])[t] = v;
    ((float4*)g_s_val[b][s])[t]   = v;
}

__global__ void k_bcast(const float* __restrict__ pe, int which) {
    int b = blockIdx.y, n = blockIdx.x, t = threadIdx.x;
    float4 v = ((const float4*)(pe + (long long)n * DIMS))[t];
    ((float4*)(arr_state(which, b) + (long long)n * DIMS))[t] = v;
    ((float4*)(arr_val(which, b)   + (long long)n * DIMS))[t] = v;
}

// ---------------- causal window propagation (window=4) into tmp ----------------
__global__ void k_winprop(const float* __restrict__ w) {
    __shared__ float sm[4][4];
    int b = blockIdx.y, i = blockIdx.x, t = threadIdx.x;
    const float* sS = &g_s_state[b][0][0];
    const float* sV = &g_s_val[b][0][0];
    float4 q  = ((const float4*)(sS + (long long)i * DIMS))[t];
    float4 wv = ((const float4*)w)[t];
    q.x *= wv.x; q.y *= wv.y; q.z *= wv.z; q.w *= wv.w;
    float dot[4];
#pragma unroll
    for (int k = 1; k <= 4; k++) {
        float d = 0.f;
        if (i >= k) {
            float4 s = ((const float4*)(sS + (long long)(i - k) * DIMS))[t];
            d = q.x * s.x + q.y * s.y + q.z * s.z + q.w * s.w;
        }
        dot[k - 1] = d;
    }
#pragma unroll
    for (int o = 16; o; o >>= 1) {
#pragma unroll
        for (int k = 0; k < 4; k++) dot[k] += __shfl_xor_sync(0xffffffffu, dot[k], o);
    }
    int wd = t >> 5;
    if ((t & 31) == 0) { sm[wd][0] = dot[0]; sm[wd][1] = dot[1]; sm[wd][2] = dot[2]; sm[wd][3] = dot[3]; }
    __syncthreads();
    float sc[4];
#pragma unroll
    for (int k = 0; k < 4; k++) sc[k] = sm[0][k] + sm[1][k] + sm[2][k] + sm[3][k];
    int nv = i < 4 ? i : 4;
    float p[4] = {0.f, 0.f, 0.f, 0.f};
    if (nv > 0) {
        float mx = -1e30f;
        for (int j = 0; j < nv; j++) mx = fmaxf(mx, sc[j]);
        float sum = 0.f;
        for (int j = 0; j < nv; j++) { p[j] = expf(sc[j] - mx); sum += p[j]; }
        float inv = 1.f / sum;
        for (int j = 0; j < nv; j++) p[j] *= inv;
    }
    float4 os = {0, 0, 0, 0}, ov = {0, 0, 0, 0};
    for (int j = 0; j < nv; j++) {
        float4 s = ((const float4*)(sS + (long long)(i - 1 - j) * DIMS))[t];
        float4 v = ((const float4*)(sV + (long long)(i - 1 - j) * DIMS))[t];
        os.x += p[j] * s.x; os.y += p[j] * s.y; os.z += p[j] * s.z; os.w += p[j] * s.w;
        ov.x += p[j] * v.x; ov.y += p[j] * v.y; ov.z += p[j] * v.z; ov.w += p[j] * v.w;
    }
    ((float4*)g_tmp_state[b][i])[t] = os;
    ((float4*)g_tmp_val[b][i])[t]   = ov;
}

// ---------------- dst += coef * tmp ----------------
__global__ void k_apply(int which, int N, float coef) {
    int b = blockIdx.y;
    long long idx = (long long)blockIdx.x * blockDim.x + threadIdx.x;
    long long tot = (long long)N * (DIMS / 4);
    if (idx >= tot) return;
    float4* st = (float4*)arr_state(which, b);
    float4* vl = (float4*)arr_val(which, b);
    const float4* ts = (const float4*)&g_tmp_state[b][0][0];
    const float4* tv = (const float4*)&g_tmp_val[b][0][0];
    float4 a = st[idx], d = ts[idx];
    a.x += coef * d.x; a.y += coef * d.y; a.z += coef * d.z; a.w += coef * d.w;
    st[idx] = a;
    float4 c = vl[idx], e = tv[idx];
    c.x += coef * e.x; c.y += coef * e.y; c.z += coef * e.z; c.w += coef * e.w;
    vl[idx] = c;
}

// ---------------- split conversions ----------------
// A side (dst state * w): segments [hi, hi, lo]
__global__ void k_split_dst(int which, const float* __restrict__ w) {
    int b = blockIdx.y, row = blockIdx.x, t = threadIdx.x;
    const float* src = arr_state(which, b) + (long long)row * DIMS;
    float4 x = ((const float4*)src)[t];
    float4 ww = ((const float4*)w)[t];
    x.x *= ww.x; x.y *= ww.y; x.z *= ww.z; x.w *= ww.w;
    __nv_bfloat16 h0 = __float2bfloat16_rn(x.x), h1 = __float2bfloat16_rn(x.y);
    __nv_bfloat16 h2 = __float2bfloat16_rn(x.z), h3 = __float2bfloat16_rn(x.w);
    __nv_bfloat162 hp0(h0, h1), hp1(h2, h3);
    __nv_bfloat162 lp0(__float2bfloat16_rn(x.x - __bfloat162float(h0)),
                       __float2bfloat16_rn(x.y - __bfloat162float(h1)));
    __nv_bfloat162 lp1(__float2bfloat16_rn(x.z - __bfloat162float(h2)),
                       __float2bfloat16_rn(x.w - __bfloat162float(h3)));
    __nv_bfloat16* out = g_A2 + ((size_t)b * EMAX + row) * K2;
    ((__nv_bfloat162*)out)[t * 2]              = hp0;
    ((__nv_bfloat162*)out)[t * 2 + 1]          = hp1;
    ((__nv_bfloat162*)(out + 512))[t * 2]      = hp0;
    ((__nv_bfloat162*)(out + 512))[t * 2 + 1]  = hp1;
    ((__nv_bfloat162*)(out + 1024))[t * 2]     = lp0;
    ((__nv_bfloat162*)(out + 1024))[t * 2 + 1] = lp1;
}

// B side (src state): segments [hi, lo, hi]
__global__ void k_split_src(int which) {
    int b = blockIdx.y, row = blockIdx.x, t = threadIdx.x;
    const float* src = arr_state(which, b) + (long long)row * DIMS;
    float4 x = ((const float4*)src)[t];
    __nv_bfloat16 h0 = __float2bfloat16_rn(x.x), h1 = __float2bfloat16_rn(x.y);
    __nv_bfloat16 h2 = __float2bfloat16_rn(x.z), h3 = __float2bfloat16_rn(x.w);
    __nv_bfloat162 hp0(h0, h1), hp1(h2, h3);
    __nv_bfloat162 lp0(__float2bfloat16_rn(x.x - __bfloat162float(h0)),
                       __float2bfloat16_rn(x.y - __bfloat162float(h1)));
    __nv_bfloat162 lp1(__float2bfloat16_rn(x.z - __bfloat162float(h2)),
                       __float2bfloat16_rn(x.w - __bfloat162float(h3)));
    __nv_bfloat16* out = g_B2 + ((size_t)b * EMAX + row) * K2;
    ((__nv_bfloat162*)out)[t * 2]              = hp0;
    ((__nv_bfloat162*)out)[t * 2 + 1]          = hp1;
    ((__nv_bfloat162*)(out + 512))[t * 2]      = lp0;
    ((__nv_bfloat162*)(out + 512))[t * 2 + 1]  = lp1;
    ((__nv_bfloat162*)(out + 1024))[t * 2]     = hp0;
    ((__nv_bfloat162*)(out + 1024))[t * 2 + 1] = hp1;
}

// readout A: s_val flat (4096 rows), segments [hi, hi, lo]
__global__ void k_split_a_flat() {
    int row = blockIdx.x, t = threadIdx.x;
    const float* src = &g_s_val[0][0][0] + (long long)row * DIMS;
    float4 x = ((const float4*)src)[t];
    __nv_bfloat16 h0 = __float2bfloat16_rn(x.x), h1 = __float2bfloat16_rn(x.y);
    __nv_bfloat16 h2 = __float2bfloat16_rn(x.z), h3 = __float2bfloat16_rn(x.w);
    __nv_bfloat162 hp0(h0, h1), hp1(h2, h3);
    __nv_bfloat162 lp0(__float2bfloat16_rn(x.x - __bfloat162float(h0)),
                       __float2bfloat16_rn(x.y - __bfloat162float(h1)));
    __nv_bfloat162 lp1(__float2bfloat16_rn(x.z - __bfloat162float(h2)),
                       __float2bfloat16_rn(x.w - __bfloat162float(h3)));
    __nv_bfloat16* out = g_A2 + (size_t)row * K2;
    ((__nv_bfloat162*)out)[t * 2]              = hp0;
    ((__nv_bfloat162*)out)[t * 2 + 1]          = hp1;
    ((__nv_bfloat162*)(out + 512))[t * 2]      = hp0;
    ((__nv_bfloat162*)(out + 512))[t * 2 + 1]  = hp1;
    ((__nv_bfloat162*)(out + 1024))[t * 2]     = lp0;
    ((__nv_bfloat162*)(out + 1024))[t * 2 + 1] = lp1;
}

// readout W: transpose [512][32000] -> g_W2 [32000][K2], segments [hi, lo, hi]
__global__ void k_split_w(const float* __restrict__ W) {
    __shared__ float tile[32][33];
    int n0 = blockIdx.x * 32, k0 = blockIdx.y * 32;
    int tx = threadIdx.x, ty = threadIdx.y;  // 32 x 8
#pragma unroll
    for (int j = 0; j < 4; j++)
        tile[ty + j * 8][tx] = W[(size_t)(k0 + ty + j * 8) * NV + n0 + tx];
    __syncthreads();
#pragma unroll
    for (int j = 0; j < 4; j++) {
        int n = n0 + ty + j * 8;
        float x = tile[tx][ty + j * 8];          // = W[k0+tx][n]
        __nv_bfloat16 h = __float2bfloat16_rn(x);
        __nv_bfloat16 l = __float2bfloat16_rn(x - __bfloat162float(h));
        __nv_bfloat16* out = g_W2 + (size_t)n * K2 + k0 + tx;
        out[0]    = h;
        out[512]  = l;
        out[1024] = h;
    }
}

// ---------------- mma.sync bf16 GEMM (3-stage cp.async pipeline) ----------------
// C[M,N] = A2[M,K2] @ B2[N,K2]^T. Block 128x128, 8 warps, warp tile 64x32.
// k-chunk 32, THREE smem stages (dynamic smem), 2 chunks in flight during compute.
#define SPAD 40                       // elems per smem row (80 B stride, conflict-free, 16B-aligned)
#define STG_ELEM (128 * SPAD)         // bf16 elems per stage
#define STG_BYTE (STG_ELEM * 2)
#define GEMM_DYN_SMEM (6 * STG_BYTE)  // 3 stages x (A + B) = 61440 B
__global__ __launch_bounds__(256) void k_mma_gemm(int M, int N, long long ldc,
                                                  long long sa, long long sb, long long sc,
                                                  int useW, float* __restrict__ Cout,
                                                  const float* __restrict__ bias) {
    extern __shared__ __align__(16) char dynsm[];
    __nv_bfloat16* sA = (__nv_bfloat16*)dynsm;                        // 3 * STG_ELEM
    __nv_bfloat16* sB = (__nv_bfloat16*)(dynsm + 3 * STG_BYTE);       // 3 * STG_ELEM
    const __nv_bfloat16* A2 = g_A2 + (size_t)blockIdx.z * sa;
    const __nv_bfloat16* B2 = (useW ? g_W2 : g_B2) + (size_t)blockIdx.z * sb;
    float* C = (Cout ? Cout : &g_scores[0][0]) + (size_t)blockIdx.z * sc;

    int tid = threadIdx.x, lane = tid & 31, wid = tid >> 5;
    int wm = wid >> 2, wn = wid & 3;
    int m0 = blockIdx.y * 128, n0 = blockIdx.x * 128;

    // cp.async assignment: f in {tid, tid+256}; row = f>>2, cq = f&3 (16B chunk in 64B row)
    int rowA0 = tid >> 2,       cq0 = tid & 3;
    int rowA1 = (tid + 256) >> 2, cq1 = tid & 3;   // (tid+256)&3 == tid&3
    const __nv_bfloat16* gA0 = A2 + (size_t)min(m0 + rowA0, M - 1) * K2 + cq0 * 8;
    const __nv_bfloat16* gA1 = A2 + (size_t)min(m0 + rowA1, M - 1) * K2 + cq1 * 8;
    const __nv_bfloat16* gB0 = B2 + (size_t)min(n0 + rowA0, N - 1) * K2 + cq0 * 8;
    const __nv_bfloat16* gB1 = B2 + (size_t)min(n0 + rowA1, N - 1) * K2 + cq1 * 8;
    uint32_t sA0 = smem_u32(sA) + (uint32_t)(rowA0 * SPAD + cq0 * 8) * 2;
    uint32_t sA1 = smem_u32(sA) + (uint32_t)(rowA1 * SPAD + cq1 * 8) * 2;
    uint32_t sB0 = smem_u32(sB) + (uint32_t)(rowA0 * SPAD + cq0 * 8) * 2;
    uint32_t sB1 = smem_u32(sB) + (uint32_t)(rowA1 * SPAD + cq1 * 8) * 2;

    float acc[4][4][4];
#pragma unroll
    for (int i = 0; i < 4; i++)
#pragma unroll
        for (int j = 0; j < 4; j++)
#pragma unroll
            for (int q = 0; q < 4; q++) acc[i][j][q] = 0.f;

    uint32_t aBase = smem_u32(sA) + (uint32_t)(((wm * 64 + (lane & 15)) * SPAD + (lane >> 4) * 8) * 2);
    uint32_t bBase = smem_u32(sB) + (uint32_t)(((wn * 32 + (lane & 7)) * SPAD + ((lane >> 3) & 1) * 8) * 2);

    const int NCH = K2 / 32;  // 48 chunks
    // prefill chunks 0,1 -> stages 0,1 (one commit group per chunk)
#pragma unroll
    for (int p = 0; p < 2; p++) {
        uint32_t so = (uint32_t)p * STG_BYTE;
        int kk = p * 32;
        cp16(sA0 + so, gA0 + kk); cp16(sA1 + so, gA1 + kk);
        cp16(sB0 + so, gB0 + kk); cp16(sB1 + so, gB1 + kk);
        CP_COMMIT();
    }
    int st = 0;  // stage holding chunk c
    for (int c = 0; c < NCH; c++) {
        if (c + 1 < NCH) { CP_WAIT1(); }   // drain chunk c; chunk c+1 may stay in flight
        else             { CP_WAIT0(); }   // last chunk: drain everything
        __syncthreads();                   // all threads done reading stage (c+2)%3 (iter c-1)
        if (c + 2 < NCH) {
            int wst = st + 2; if (wst >= 3) wst -= 3;
            uint32_t so = (uint32_t)wst * STG_BYTE;
            int k1 = (c + 2) * 32;
            cp16(sA0 + so, gA0 + k1); cp16(sA1 + so, gA1 + k1);
            cp16(sB0 + so, gB0 + k1); cp16(sB1 + so, gB1 + k1);
            CP_COMMIT();
        }
        uint32_t bo = (uint32_t)st * STG_BYTE;
#pragma unroll
        for (int sub = 0; sub < 2; sub++) {
            uint32_t ko = sub * 32;  // 16 elems * 2 B
            uint32_t afr[4][4], bfr[4][2];
#pragma unroll
            for (int mi = 0; mi < 4; mi++) ldm_x4(afr[mi], aBase + bo + ko + mi * (16 * SPAD * 2));
#pragma unroll
            for (int ni = 0; ni < 4; ni++) ldm_x2(bfr[ni], bBase + bo + ko + ni * (8 * SPAD * 2));
#pragma unroll
            for (int mi = 0; mi < 4; mi++)
#pragma unroll
                for (int ni = 0; ni < 4; ni++) mma_bf16(acc[mi][ni], afr[mi], bfr[ni]);
        }
        st++; if (st == 3) st = 0;
    }

    // epilogue
    int rb0 = m0 + wm * 64 + (lane >> 2);
    int cb0 = n0 + wn * 32 + (lane & 3) * 2;
#pragma unroll
    for (int mi = 0; mi < 4; mi++) {
#pragma unroll
        for (int ni = 0; ni < 4; ni++) {
            int r = rb0 + mi * 16;
            int cc = cb0 + ni * 8;
            float b0 = 0.f, b1 = 0.f;
            if (bias) {
                if (cc < N) b0 = bias[cc];
                if (cc + 1 < N) b1 = bias[cc + 1];
            }
            if (r < M) {
                if (cc < N)     C[(size_t)r * ldc + cc]     = acc[mi][ni][0] + b0;
                if (cc + 1 < N) C[(size_t)r * ldc + cc + 1] = acc[mi][ni][1] + b1;
            }
            if (r + 8 < M) {
                if (cc < N)     C[(size_t)(r + 8) * ldc + cc]     = acc[mi][ni][2] + b0;
                if (cc + 1 < N) C[(size_t)(r + 8) * ldc + cc + 1] = acc[mi][ni][3] + b1;
            }
        }
    }
}

// ---------------- fused per-row top-4 + softmax + gather ----------------
__global__ void k_topk_gather(int N, int srcW, int acc) {
    __shared__ float sv[512];
    __shared__ int   si[512];
    __shared__ float sp[4];
    __shared__ int   sx[4];
    int b = blockIdx.y, n = blockIdx.x, t = threadIdx.x;
    const float* row = g_scores[b] + (long long)n * SLD;
    float v0 = -3e38f, v1 = -3e38f, v2 = -3e38f, v3 = -3e38f;
    int   i0 = 0x7fffffff, i1 = 0x7fffffff, i2 = 0x7fffffff, i3 = 0x7fffffff;
    for (int s = t; s < N; s += 128) {
        float v = row[s];
        bool c3 = (v > v3) || (v == v3 && s < i3);
        if (c3) {
            bool c0 = (v > v0) || (v == v0 && s < i0);
            bool c1 = (v > v1) || (v == v1 && s < i1);
            bool c2 = (v > v2) || (v == v2 && s < i2);
            if (c0)      { v3 = v2; i3 = i2; v2 = v1; i2 = i1; v1 = v0; i1 = i0; v0 = v; i0 = s; }
            else if (c1) { v3 = v2; i3 = i2; v2 = v1; i2 = i1; v1 = v; i1 = s; }
            else if (c2) { v3 = v2; i3 = i2; v2 = v; i2 = s; }
            else         { v3 = v; i3 = s; }
        }
    }
    sv[t * 4 + 0] = v0; si[t * 4 + 0] = i0;
    sv[t * 4 + 1] = v1; si[t * 4 + 1] = i1;
    sv[t * 4 + 2] = v2; si[t * 4 + 2] = i2;
    sv[t * 4 + 3] = v3; si[t * 4 + 3] = i3;
    __syncthreads();
    if (t == 0) {
        float w0 = -3e38f, w1 = -3e38f, w2 = -3e38f, w3 = -3e38f;
        int   j0 = 0x7fffffff, j1 = j0, j2 = j0, j3 = j0;
        for (int q = 0; q < 512; q++) {
            float v = sv[q]; int s = si[q];
            bool c3 = (v > w3) || (v == w3 && s < j3);
            if (c3) {
                bool c0 = (v > w0) || (v == w0 && s < j0);
                bool c1 = (v > w1) || (v == w1 && s < j1);
                bool c2 = (v > w2) || (v == w2 && s < j2);
                if (c0)      { w3 = w2; j3 = j2; w2 = w1; j2 = j1; w1 = w0; j1 = j0; w0 = v; j0 = s; }
                else if (c1) { w3 = w2; j3 = j2; w2 = w1; j2 = j1; w1 = v; j1 = s; }
                else if (c2) { w3 = w2; j3 = j2; w2 = v; j2 = s; }
                else         { w3 = v; j3 = s; }
            }
        }
        float e0 = 1.f, e1 = expf(w1 - w0), e2 = expf(w2 - w0), e3 = expf(w3 - w0);
        float inv = 1.f / (e0 + e1 + e2 + e3);
        sp[0] = e0 * inv; sp[1] = e1 * inv; sp[2] = e2 * inv; sp[3] = e3 * inv;
        sx[0] = j0; sx[1] = j1; sx[2] = j2; sx[3] = j3;
    }
    __syncthreads();
    const float* ss = arr_state(srcW, b);
    const float* svp = arr_val(srcW, b);
    float p0 = sp[0], p1 = sp[1], p2 = sp[2], p3 = sp[3];
    int a0 = sx[0], a1 = sx[1], a2 = sx[2], a3 = sx[3];
    float4 os = {0, 0, 0, 0}, ov = {0, 0, 0, 0};
    float4 x, y;
    x = ((const float4*)(ss + (long long)a0 * DIMS))[t]; y = ((const float4*)(svp + (long long)a0 * DIMS))[t];
    os.x += p0 * x.x; os.y += p0 * x.y; os.z += p0 * x.z; os.w += p0 * x.w;
    ov.x += p0 * y.x; ov.y += p0 * y.y; ov.z += p0 * y.z; ov.w += p0 * y.w;
    x = ((const float4*)(ss + (long long)a1 * DIMS))[t]; y = ((const float4*)(svp + (long long)a1 * DIMS))[t];
    os.x += p1 * x.x; os.y += p1 * x.y; os.z += p1 * x.z; os.w += p1 * x.w;
    ov.x += p1 * y.x; ov.y += p1 * y.y; ov.z += p1 * y.z; ov.w += p1 * y.w;
    x = ((const float4*)(ss + (long long)a2 * DIMS))[t]; y = ((const float4*)(svp + (long long)a2 * DIMS))[t];
    os.x += p2 * x.x; os.y += p2 * x.y; os.z += p2 * x.z; os.w += p2 * x.w;
    ov.x += p2 * y.x; ov.y += p2 * y.y; ov.z += p2 * y.z; ov.w += p2 * y.w;
    x = ((const float4*)(ss + (long long)a3 * DIMS))[t]; y = ((const float4*)(svp + (long long)a3 * DIMS))[t];
    os.x += p3 * x.x; os.y += p3 * x.y; os.z += p3 * x.z; os.w += p3 * x.w;
    ov.x += p3 * y.x; ov.y += p3 * y.y; ov.z += p3 * y.z; ov.w += p3 * y.w;
    float4* ts = (float4*)g_tmp_state[b][n];
    float4* tv = (float4*)g_tmp_val[b][n];
    if (acc) {
        float4 u = ts[t]; os.x += u.x; os.y += u.y; os.z += u.z; os.w += u.w;
        float4 v = tv[t]; ov.x += v.x; ov.y += v.y; ov.z += v.z; ov.w += v.w;
    }
    ts[t] = os;
    tv[t] = ov;
}

// ---------------- stabilize: state=tanh(state); val=LayerNorm(val) ----------------
__device__ __forceinline__ float blk_sum(float v, float* sm, int t) {
#pragma unroll
    for (int o = 16; o; o >>= 1) v += __shfl_xor_sync(0xffffffffu, v, o);
    if ((t & 31) == 0) sm[t >> 5] = v;
    __syncthreads();
    v = sm[0] + sm[1] + sm[2] + sm[3];
    __syncthreads();
    return v;
}

__global__ void k_stabilize(int which, const float* __restrict__ g, const float* __restrict__ be) {
    __shared__ float sm[4];
    int b = blockIdx.y, n = blockIdx.x, t = threadIdx.x;
    float* st = arr_state(which, b) + (long long)n * DIMS;
    float* vl = arr_val(which, b) + (long long)n * DIMS;
    float4 s4 = ((float4*)st)[t];
    s4.x = tanhf(s4.x); s4.y = tanhf(s4.y); s4.z = tanhf(s4.z); s4.w = tanhf(s4.w);
    ((float4*)st)[t] = s4;
    float4 v4 = ((float4*)vl)[t];
    float sum = v4.x + v4.y + v4.z + v4.w;
    sum = blk_sum(sum, sm, t);
    float mean = sum * (1.f / DIMS);
    float dx = v4.x - mean, dy = v4.y - mean, dz = v4.z - mean, dw = v4.w - mean;
    float sq = dx * dx + dy * dy + dz * dz + dw * dw;
    sq = blk_sum(sq, sm, t);
    float inv = rsqrtf(sq * (1.f / DIMS) + 1e-5f);
    float4 g4 = ((const float4*)g)[t], b4 = ((const float4*)be)[t];
    v4.x = dx * inv * g4.x + b4.x;
    v4.y = dy * inv * g4.y + b4.y;
    v4.z = dz * inv * g4.z + b4.z;
    v4.w = dw * inv * g4.w + b4.w;
    ((float4*)vl)[t] = v4;
}

// ---------------- host orchestration ----------------
extern "C" void kernel_launch(void* const* d_in, const int* in_sizes, int n_in,
                              void* d_out, int out_size) {
    (void)out_size;
    const int*   tokens    = (const int*)d_in[0];
    const float* embed     = (const float*)d_in[1];
    const float* readout_w = (const float*)d_in[2];
    const float* readout_b = (const float*)d_in[3];
    const float* w_s   = (const float*)d_in[4];
    const float* w_se  = (const float*)d_in[5];
    const float* w_sc  = (const float*)d_in[6];
    const float* w_s2e = (const float*)d_in[7];
    const float* w_e2s = (const float*)d_in[8];
    const float* w_s2c = (const float*)d_in[9];
    const float* w_c2s = (const float*)d_in[10];
    const float* ln_s_g = (const float*)d_in[11];
    const float* ln_s_b = (const float*)d_in[12];
    const float* ln_e_g = (const float*)d_in[13];
    const float* ln_e_b = (const float*)d_in[14];
    const float* ln_c_g = (const float*)d_in[15];
    const float* ln_c_b = (const float*)d_in[16];

    static const int NE[3] = {2151, 2253, 2458};
    static const int NC[3] = {1844, 1639, 1434};
    const float* pe_e[3] = {0, 0, 0};
    const float* pe_c[3] = {0, 0, 0};
    for (int i = 17; i < n_in; i++) {
        long long sz = in_sizes[i];
        for (int st = 0; st < 3; st++) {
            if (sz == (long long)NE[st] * DIMS) pe_e[st] = (const float*)d_in[i];
            if (sz == (long long)NC[st] * DIMS) pe_c[st] = (const float*)d_in[i];
        }
    }

    const float AL[3][3] = {{0.3f, 0.25f, 0.15f}, {0.65f, 0.55f, 0.35f}, {1.0f, 0.9f, 0.8f}};
    const int STL[3] = {2, 2, 1};

    cudaFuncSetAttribute(k_mma_gemm, cudaFuncAttributeMaxDynamicSharedMemorySize, GEMM_DYN_SMEM);

    auto applyK = [&](int which, int N, float coef) {
        long long tot = (long long)N * (DIMS / 4);
        int blocks = (int)((tot + 255) / 256);
        k_apply<<<dim3(blocks, NBATCH), 256>>>(which, N, coef);
    };
    auto attend = [&](int dstW, int srcW, int M, int N, const float* w, int acc, int doSrc) {
        k_split_dst<<<dim3(M, NBATCH), 128>>>(dstW, w);
        if (doSrc) k_split_src<<<dim3(N, NBATCH), 128>>>(srcW);
        k_mma_gemm<<<dim3((N + 127) / 128, (M + 127) / 128, NBATCH), 256, GEMM_DYN_SMEM>>>(
            M, N, SLD, (long long)EMAX * K2, (long long)EMAX * K2, (long long)EMAX * SLD,
            0, nullptr, nullptr);
        k_topk_gather<<<dim3(M, NBATCH), 128>>>(N, srcW, acc);
    };

    k_embed_init<<<dim3(SEQL, NBATCH), 128>>>(tokens, embed);

    int li = 0;
    for (int st = 0; st < 3; st++) {
        int ne = NE[st], nc = NC[st];
        float alpha = AL[st][0], bs2b = AL[st][1], bb2s = AL[st][2];
        k_bcast<<<dim3(ne, NBATCH), 128>>>(pe_e[st], 1);
        k_bcast<<<dim3(nc, NBATCH), 128>>>(pe_c[st], 2);
        for (int l = 0; l < STL[st]; l++) {
            k_winprop<<<dim3(SEQL, NBATCH), 128>>>(w_s + li * DIMS);
            applyK(0, SEQL, 0.25f);
            // s_state unchanged between the two S-source attends: split src once
            attend(1, 0, ne, SEQL, w_s2e + li * DIMS, 0, 1); applyK(1, ne, 0.15f * bs2b * alpha);
            attend(2, 0, nc, SEQL, w_s2c + li * DIMS, 0, 0); applyK(2, nc, 0.15f * bs2b * alpha);
            attend(1, 1, ne, ne, w_se + li * DIMS, 0, 1);    applyK(1, ne, 0.2f * alpha);
            attend(2, 2, nc, nc, w_sc + li * DIMS, 0, 1);    applyK(2, nc, 0.2f * alpha);
            attend(0, 1, SEQL, ne, w_e2s + li * DIMS, 0, 1);
            attend(0, 2, SEQL, nc, w_c2s + li * DIMS, 1, 1);
            applyK(0, SEQL, 0.15f * bb2s);
            k_stabilize<<<dim3(SEQL, NBATCH), 128>>>(0, ln_s_g + li * DIMS, ln_s_b + li * DIMS);
            k_stabilize<<<dim3(ne, NBATCH), 128>>>(1, ln_e_g + li * DIMS, ln_e_b + li * DIMS);
            k_stabilize<<<dim3(nc, NBATCH), 128>>>(2, ln_c_g + li * DIMS, ln_c_b + li * DIMS);
            li++;
        }
    }

    // readout: split conversions + tensor-core GEMM
    k_split_a_flat<<<NBATCH * SEQL, 128>>>();
    k_split_w<<<dim3(NV / 32, DIMS / 32), dim3(32, 8)>>>(readout_w);
    k_mma_gemm<<<dim3(NV / 128, (NBATCH * SEQL) / 128, 1), 256, GEMM_DYN_SMEM>>>(
        NBATCH * SEQL, NV, NV, 0, 0, 0, 1, (float*)d_out, readout_b);
}

// round 13
// speedup vs baseline: 1.6189x; 1.6189x over previous
#include <cuda_runtime.h>
#include <cuda_bf16.h>
#include <cstdint>

#define DIMS 512
#define K2   1536    // split-expanded K (3 * DIMS)
#define SEQL 2048
#define NBATCH 2
#define EMAX 2458
#define CMAX 1844
#define SLD  2464   // padded score row stride
#define NV   32000

// ---------------- device scratch (static: no allocs allowed) ----------------
__device__ float g_s_state[NBATCH][SEQL][DIMS];
__device__ float g_s_val  [NBATCH][SEQL][DIMS];
__device__ float g_e_state[NBATCH][EMAX][DIMS];
__device__ float g_e_val  [NBATCH][EMAX][DIMS];
__device__ float g_c_state[NBATCH][CMAX][DIMS];
__device__ float g_c_val  [NBATCH][CMAX][DIMS];
__device__ float g_tmp_state[NBATCH][EMAX][DIMS];
__device__ float g_tmp_val  [NBATCH][EMAX][DIMS];
__device__ float g_scores[NBATCH][EMAX * SLD];
// split-bf16 expanded operands
__device__ __nv_bfloat16 g_A2[(size_t)NBATCH * EMAX * K2];   // A side: [hi, hi, lo]
__device__ __nv_bfloat16 g_B2[(size_t)NBATCH * EMAX * K2];   // B side: [hi, lo, hi]
__device__ __nv_bfloat16 g_W2[(size_t)NV * K2];              // readout W^T split: [hi, lo, hi]

__device__ __forceinline__ float* arr_state(int w, int b) {
    if (w == 0) return &g_s_state[b][0][0];
    if (w == 1) return &g_e_state[b][0][0];
    if (w == 2) return &g_c_state[b][0][0];
    return &g_tmp_state[b][0][0];
}
__device__ __forceinline__ float* arr_val(int w, int b) {
    if (w == 0) return &g_s_val[b][0][0];
    if (w == 1) return &g_e_val[b][0][0];
    if (w == 2) return &g_c_val[b][0][0];
    return &g_tmp_val[b][0][0];
}

__device__ __forceinline__ uint32_t smem_u32(const void* p) {
    uint32_t a;
    asm("{ .reg .u64 t; cvta.to.shared.u64 t, %1; cvt.u32.u64 %0, t; }" : "=r"(a) : "l"(p));
    return a;
}
__device__ __forceinline__ void ldm_x4(uint32_t* r, uint32_t addr) {
    asm volatile("ldmatrix.sync.aligned.m8n8.x4.shared.b16 {%0,%1,%2,%3}, [%4];"
                 : "=r"(r[0]), "=r"(r[1]), "=r"(r[2]), "=r"(r[3]) : "r"(addr));
}
__device__ __forceinline__ void ldm_x2(uint32_t* r, uint32_t addr) {
    asm volatile("ldmatrix.sync.aligned.m8n8.x2.shared.b16 {%0,%1}, [%2];"
                 : "=r"(r[0]), "=r"(r[1]) : "r"(addr));
}
__device__ __forceinline__ void mma_bf16(float* c, const uint32_t* a, const uint32_t* b) {
    asm volatile("mma.sync.aligned.m16n8k16.row.col.f32.bf16.bf16.f32 "
                 "{%0,%1,%2,%3}, {%4,%5,%6,%7}, {%8,%9}, {%0,%1,%2,%3};"
                 : "+f"(c[0]), "+f"(c[1]), "+f"(c[2]), "+f"(c[3])
                 : "r"(a[0]), "r"(a[1]), "r"(a[2]), "r"(a[3]), "r"(b[0]), "r"(b[1]));
}
__device__ __forceinline__ void cp16(uint32_t saddr, const void* gaddr) {
    asm volatile("cp.async.cg.shared.global [%0], [%1], 16;" :: "r"(saddr), "l"(gaddr));
}
#define CP_COMMIT() asm volatile("cp.async.commit_group;" ::: "memory")
#define CP_WAIT0()  asm volatile("cp.async.wait_group 0;" ::: "memory")

// ---------------- init kernels ----------------
__global__ void k_embed_init(const int* __restrict__ tokens, const float* __restrict__ embed) {
    int b = blockIdx.y, s = blockIdx.x, t = threadIdx.x;
    int tok = tokens[b * SEQL + s];
    float4 v = ((const float4*)(embed + (long long)tok * DIMS))[t];
    ((float4*)g_s_state[b][s])[t] = v;
    ((float4*)g_s_val[b][s])[t]   = v;
}

__global__ void k_bcast(const float* __restrict__ pe, int which) {
    int b = blockIdx.y, n = blockIdx.x, t = threadIdx.x;
    float4 v = ((const float4*)(pe + (long long)n * DIMS))[t];
    ((float4*)(arr_state(which, b) + (long long)n * DIMS))[t] = v;
    ((float4*)(arr_val(which, b)   + (long long)n * DIMS))[t] = v;
}

// ---------------- causal window propagation (window=4) into tmp ----------------
__global__ void k_winprop(const float* __restrict__ w) {
    __shared__ float sm[4][4];
    int b = blockIdx.y, i = blockIdx.x, t = threadIdx.x;
    const float* sS = &g_s_state[b][0][0];
    const float* sV = &g_s_val[b][0][0];
    float4 q  = ((const float4*)(sS + (long long)i * DIMS))[t];
    float4 wv = ((const float4*)w)[t];
    q.x *= wv.x; q.y *= wv.y; q.z *= wv.z; q.w *= wv.w;
    float dot[4];
#pragma unroll
    for (int k = 1; k <= 4; k++) {
        float d = 0.f;
        if (i >= k) {
            float4 s = ((const float4*)(sS + (long long)(i - k) * DIMS))[t];
            d = q.x * s.x + q.y * s.y + q.z * s.z + q.w * s.w;
        }
        dot[k - 1] = d;
    }
#pragma unroll
    for (int o = 16; o; o >>= 1) {
#pragma unroll
        for (int k = 0; k < 4; k++) dot[k] += __shfl_xor_sync(0xffffffffu, dot[k], o);
    }
    int wd = t >> 5;
    if ((t & 31) == 0) { sm[wd][0] = dot[0]; sm[wd][1] = dot[1]; sm[wd][2] = dot[2]; sm[wd][3] = dot[3]; }
    __syncthreads();
    float sc[4];
#pragma unroll
    for (int k = 0; k < 4; k++) sc[k] = sm[0][k] + sm[1][k] + sm[2][k] + sm[3][k];
    int nv = i < 4 ? i : 4;
    float p[4] = {0.f, 0.f, 0.f, 0.f};
    if (nv > 0) {
        float mx = -1e30f;
        for (int j = 0; j < nv; j++) mx = fmaxf(mx, sc[j]);
        float sum = 0.f;
        for (int j = 0; j < nv; j++) { p[j] = expf(sc[j] - mx); sum += p[j]; }
        float inv = 1.f / sum;
        for (int j = 0; j < nv; j++) p[j] *= inv;
    }
    float4 os = {0, 0, 0, 0}, ov = {0, 0, 0, 0};
    for (int j = 0; j < nv; j++) {
        float4 s = ((const float4*)(sS + (long long)(i - 1 - j) * DIMS))[t];
        float4 v = ((const float4*)(sV + (long long)(i - 1 - j) * DIMS))[t];
        os.x += p[j] * s.x; os.y += p[j] * s.y; os.z += p[j] * s.z; os.w += p[j] * s.w;
        ov.x += p[j] * v.x; ov.y += p[j] * v.y; ov.z += p[j] * v.z; ov.w += p[j] * v.w;
    }
    ((float4*)g_tmp_state[b][i])[t] = os;
    ((float4*)g_tmp_val[b][i])[t]   = ov;
}

// ---------------- dst += coef * tmp ----------------
__global__ void k_apply(int which, int N, float coef) {
    int b = blockIdx.y;
    long long idx = (long long)blockIdx.x * blockDim.x + threadIdx.x;
    long long tot = (long long)N * (DIMS / 4);
    if (idx >= tot) return;
    float4* st = (float4*)arr_state(which, b);
    float4* vl = (float4*)arr_val(which, b);
    const float4* ts = (const float4*)&g_tmp_state[b][0][0];
    const float4* tv = (const float4*)&g_tmp_val[b][0][0];
    float4 a = st[idx], d = ts[idx];
    a.x += coef * d.x; a.y += coef * d.y; a.z += coef * d.z; a.w += coef * d.w;
    st[idx] = a;
    float4 c = vl[idx], e = tv[idx];
    c.x += coef * e.x; c.y += coef * e.y; c.z += coef * e.z; c.w += coef * e.w;
    vl[idx] = c;
}

// ---------------- split conversions ----------------
// A side (dst state * w): segments [hi, hi, lo]
__global__ void k_split_dst(int which, const float* __restrict__ w) {
    int b = blockIdx.y, row = blockIdx.x, t = threadIdx.x;
    const float* src = arr_state(which, b) + (long long)row * DIMS;
    float4 x = ((const float4*)src)[t];
    float4 ww = ((const float4*)w)[t];
    x.x *= ww.x; x.y *= ww.y; x.z *= ww.z; x.w *= ww.w;
    __nv_bfloat16 h0 = __float2bfloat16_rn(x.x), h1 = __float2bfloat16_rn(x.y);
    __nv_bfloat16 h2 = __float2bfloat16_rn(x.z), h3 = __float2bfloat16_rn(x.w);
    __nv_bfloat162 hp0(h0, h1), hp1(h2, h3);
    __nv_bfloat162 lp0(__float2bfloat16_rn(x.x - __bfloat162float(h0)),
                       __float2bfloat16_rn(x.y - __bfloat162float(h1)));
    __nv_bfloat162 lp1(__float2bfloat16_rn(x.z - __bfloat162float(h2)),
                       __float2bfloat16_rn(x.w - __bfloat162float(h3)));
    __nv_bfloat16* out = g_A2 + ((size_t)b * EMAX + row) * K2;
    ((__nv_bfloat162*)out)[t * 2]              = hp0;
    ((__nv_bfloat162*)out)[t * 2 + 1]          = hp1;
    ((__nv_bfloat162*)(out + 512))[t * 2]      = hp0;
    ((__nv_bfloat162*)(out + 512))[t * 2 + 1]  = hp1;
    ((__nv_bfloat162*)(out + 1024))[t * 2]     = lp0;
    ((__nv_bfloat162*)(out + 1024))[t * 2 + 1] = lp1;
}

// B side (src state): segments [hi, lo, hi]
__global__ void k_split_src(int which) {
    int b = blockIdx.y, row = blockIdx.x, t = threadIdx.x;
    const float* src = arr_state(which, b) + (long long)row * DIMS;
    float4 x = ((const float4*)src)[t];
    __nv_bfloat16 h0 = __float2bfloat16_rn(x.x), h1 = __float2bfloat16_rn(x.y);
    __nv_bfloat16 h2 = __float2bfloat16_rn(x.z), h3 = __float2bfloat16_rn(x.w);
    __nv_bfloat162 hp0(h0, h1), hp1(h2, h3);
    __nv_bfloat162 lp0(__float2bfloat16_rn(x.x - __bfloat162float(h0)),
                       __float2bfloat16_rn(x.y - __bfloat162float(h1)));
    __nv_bfloat162 lp1(__float2bfloat16_rn(x.z - __bfloat162float(h2)),
                       __float2bfloat16_rn(x.w - __bfloat162float(h3)));
    __nv_bfloat16* out = g_B2 + ((size_t)b * EMAX + row) * K2;
    ((__nv_bfloat162*)out)[t * 2]              = hp0;
    ((__nv_bfloat162*)out)[t * 2 + 1]          = hp1;
    ((__nv_bfloat162*)(out + 512))[t * 2]      = lp0;
    ((__nv_bfloat162*)(out + 512))[t * 2 + 1]  = lp1;
    ((__nv_bfloat162*)(out + 1024))[t * 2]     = hp0;
    ((__nv_bfloat162*)(out + 1024))[t * 2 + 1] = hp1;
}

// readout A: s_val flat (4096 rows), segments [hi, hi, lo]
__global__ void k_split_a_flat() {
    int row = blockIdx.x, t = threadIdx.x;
    const float* src = &g_s_val[0][0][0] + (long long)row * DIMS;
    float4 x = ((const float4*)src)[t];
    __nv_bfloat16 h0 = __float2bfloat16_rn(x.x), h1 = __float2bfloat16_rn(x.y);
    __nv_bfloat16 h2 = __float2bfloat16_rn(x.z), h3 = __float2bfloat16_rn(x.w);
    __nv_bfloat162 hp0(h0, h1), hp1(h2, h3);
    __nv_bfloat162 lp0(__float2bfloat16_rn(x.x - __bfloat162float(h0)),
                       __float2bfloat16_rn(x.y - __bfloat162float(h1)));
    __nv_bfloat162 lp1(__float2bfloat16_rn(x.z - __bfloat162float(h2)),
                       __float2bfloat16_rn(x.w - __bfloat162float(h3)));
    __nv_bfloat16* out = g_A2 + (size_t)row * K2;
    ((__nv_bfloat162*)out)[t * 2]              = hp0;
    ((__nv_bfloat162*)out)[t * 2 + 1]          = hp1;
    ((__nv_bfloat162*)(out + 512))[t * 2]      = hp0;
    ((__nv_bfloat162*)(out + 512))[t * 2 + 1]  = hp1;
    ((__nv_bfloat162*)(out + 1024))[t * 2]     = lp0;
    ((__nv_bfloat162*)(out + 1024))[t * 2 + 1] = lp1;
}

// readout W: transpose [512][32000] -> g_W2 [32000][K2], segments [hi, lo, hi]
__global__ void k_split_w(const float* __restrict__ W) {
    __shared__ float tile[32][33];
    int n0 = blockIdx.x * 32, k0 = blockIdx.y * 32;
    int tx = threadIdx.x, ty = threadIdx.y;  // 32 x 8
#pragma unroll
    for (int j = 0; j < 4; j++)
        tile[ty + j * 8][tx] = W[(size_t)(k0 + ty + j * 8) * NV + n0 + tx];
    __syncthreads();
#pragma unroll
    for (int j = 0; j < 4; j++) {
        int n = n0 + ty + j * 8;
        float x = tile[tx][ty + j * 8];          // = W[k0+tx][n]
        __nv_bfloat16 h = __float2bfloat16_rn(x);
        __nv_bfloat16 l = __float2bfloat16_rn(x - __bfloat162float(h));
        __nv_bfloat16* out = g_W2 + (size_t)n * K2 + k0 + tx;
        out[0]    = h;
        out[512]  = l;
        out[1024] = h;
    }
}

// ---------------- mma.sync bf16 GEMM (2-stage cp.async pipeline, round-10 proven) ----------------
#define SPAD 40                       // elems per smem row (80 B stride, conflict-free, 16B-aligned)
#define STG_ELEM (128 * SPAD)         // bf16 elems per stage
#define STG_BYTE (STG_ELEM * 2)
__global__ __launch_bounds__(256) void k_mma_gemm(int M, int N, long long ldc,
                                                  long long sa, long long sb, long long sc,
                                                  int useW, float* __restrict__ Cout,
                                                  const float* __restrict__ bias) {
    __shared__ __align__(16) __nv_bfloat16 sA[2][STG_ELEM];
    __shared__ __align__(16) __nv_bfloat16 sB[2][STG_ELEM];
    const __nv_bfloat16* A2 = g_A2 + (size_t)blockIdx.z * sa;
    const __nv_bfloat16* B2 = (useW ? g_W2 : g_B2) + (size_t)blockIdx.z * sb;
    float* C = (Cout ? Cout : &g_scores[0][0]) + (size_t)blockIdx.z * sc;

    int tid = threadIdx.x, lane = tid & 31, wid = tid >> 5;
    int wm = wid >> 2, wn = wid & 3;
    int m0 = blockIdx.y * 128, n0 = blockIdx.x * 128;

    int rowA0 = tid >> 2,       cq0 = tid & 3;
    int rowA1 = (tid + 256) >> 2, cq1 = tid & 3;
    const __nv_bfloat16* gA0 = A2 + (size_t)min(m0 + rowA0, M - 1) * K2 + cq0 * 8;
    const __nv_bfloat16* gA1 = A2 + (size_t)min(m0 + rowA1, M - 1) * K2 + cq1 * 8;
    const __nv_bfloat16* gB0 = B2 + (size_t)min(n0 + rowA0, N - 1) * K2 + cq0 * 8;
    const __nv_bfloat16* gB1 = B2 + (size_t)min(n0 + rowA1, N - 1) * K2 + cq1 * 8;
    uint32_t sA0 = smem_u32(sA) + (uint32_t)(rowA0 * SPAD + cq0 * 8) * 2;
    uint32_t sA1 = smem_u32(sA) + (uint32_t)(rowA1 * SPAD + cq1 * 8) * 2;
    uint32_t sB0 = smem_u32(sB) + (uint32_t)(rowA0 * SPAD + cq0 * 8) * 2;
    uint32_t sB1 = smem_u32(sB) + (uint32_t)(rowA1 * SPAD + cq1 * 8) * 2;

    float acc[4][4][4];
#pragma unroll
    for (int i = 0; i < 4; i++)
#pragma unroll
        for (int j = 0; j < 4; j++)
#pragma unroll
            for (int q = 0; q < 4; q++) acc[i][j][q] = 0.f;

    uint32_t aBase = smem_u32(sA) + (uint32_t)(((wm * 64 + (lane & 15)) * SPAD + (lane >> 4) * 8) * 2);
    uint32_t bBase = smem_u32(sB) + (uint32_t)(((wn * 32 + (lane & 7)) * SPAD + ((lane >> 3) & 1) * 8) * 2);

    const int NCH = K2 / 32;  // 48 chunks
    {
        cp16(sA0, gA0); cp16(sA1, gA1);
        cp16(sB0, gB0); cp16(sB1, gB1);
        CP_COMMIT();
    }
    for (int c = 0; c < NCH; c++) {
        int buf = c & 1;
        CP_WAIT0();
        __syncthreads();
        if (c + 1 < NCH) {
            int k1 = (c + 1) * 32;
            uint32_t so = (uint32_t)(buf ^ 1) * STG_BYTE;
            cp16(sA0 + so, gA0 + k1); cp16(sA1 + so, gA1 + k1);
            cp16(sB0 + so, gB0 + k1); cp16(sB1 + so, gB1 + k1);
            CP_COMMIT();
        }
        uint32_t bo = (uint32_t)buf * STG_BYTE;
#pragma unroll
        for (int sub = 0; sub < 2; sub++) {
            uint32_t ko = sub * 32;
            uint32_t afr[4][4], bfr[4][2];
#pragma unroll
            for (int mi = 0; mi < 4; mi++) ldm_x4(afr[mi], aBase + bo + ko + mi * (16 * SPAD * 2));
#pragma unroll
            for (int ni = 0; ni < 4; ni++) ldm_x2(bfr[ni], bBase + bo + ko + ni * (8 * SPAD * 2));
#pragma unroll
            for (int mi = 0; mi < 4; mi++)
#pragma unroll
                for (int ni = 0; ni < 4; ni++) mma_bf16(acc[mi][ni], afr[mi], bfr[ni]);
        }
        __syncthreads();
    }

    // epilogue
    int rb0 = m0 + wm * 64 + (lane >> 2);
    int cb0 = n0 + wn * 32 + (lane & 3) * 2;
#pragma unroll
    for (int mi = 0; mi < 4; mi++) {
#pragma unroll
        for (int ni = 0; ni < 4; ni++) {
            int r = rb0 + mi * 16;
            int cc = cb0 + ni * 8;
            float b0 = 0.f, b1 = 0.f;
            if (bias) {
                if (cc < N) b0 = bias[cc];
                if (cc + 1 < N) b1 = bias[cc + 1];
            }
            if (r < M) {
                if (cc < N)     C[(size_t)r * ldc + cc]     = acc[mi][ni][0] + b0;
                if (cc + 1 < N) C[(size_t)r * ldc + cc + 1] = acc[mi][ni][1] + b1;
            }
            if (r + 8 < M) {
                if (cc < N)     C[(size_t)(r + 8) * ldc + cc]     = acc[mi][ni][2] + b0;
                if (cc + 1 < N) C[(size_t)(r + 8) * ldc + cc + 1] = acc[mi][ni][3] + b1;
            }
        }
    }
}

// ---------------- fused top-4 + softmax + gather (+optional apply) ----------------
// Selection logic identical (bit-exact) to the proven k_topk. Then:
//   doApply=0: tmp[n] (+)= result            (acc handled)
//   doApply=1: dst[n] += coef * result        (reads tmp first if acc)
// doApply=1 is ONLY legal when dst arrays != src arrays (no cross-block race).
__global__ void k_topk_gather(int N, int srcW, int acc, int dstW, float coef, int doApply) {
    __shared__ float sv[512];
    __shared__ int   si[512];
    __shared__ float sp[4];
    __shared__ int   sx[4];
    int b = blockIdx.y, n = blockIdx.x, t = threadIdx.x;
    const float* row = g_scores[b] + (long long)n * SLD;
    float v0 = -3e38f, v1 = -3e38f, v2 = -3e38f, v3 = -3e38f;
    int   i0 = 0x7fffffff, i1 = 0x7fffffff, i2 = 0x7fffffff, i3 = 0x7fffffff;
    for (int s = t; s < N; s += 128) {
        float v = row[s];
        bool c3 = (v > v3) || (v == v3 && s < i3);
        if (c3) {
            bool c0 = (v > v0) || (v == v0 && s < i0);
            bool c1 = (v > v1) || (v == v1 && s < i1);
            bool c2 = (v > v2) || (v == v2 && s < i2);
            if (c0)      { v3 = v2; i3 = i2; v2 = v1; i2 = i1; v1 = v0; i1 = i0; v0 = v; i0 = s; }
            else if (c1) { v3 = v2; i3 = i2; v2 = v1; i2 = i1; v1 = v; i1 = s; }
            else if (c2) { v3 = v2; i3 = i2; v2 = v; i2 = s; }
            else         { v3 = v; i3 = s; }
        }
    }
    sv[t * 4 + 0] = v0; si[t * 4 + 0] = i0;
    sv[t * 4 + 1] = v1; si[t * 4 + 1] = i1;
    sv[t * 4 + 2] = v2; si[t * 4 + 2] = i2;
    sv[t * 4 + 3] = v3; si[t * 4 + 3] = i3;
    __syncthreads();
    if (t == 0) {
        float w0 = -3e38f, w1 = -3e38f, w2 = -3e38f, w3 = -3e38f;
        int   j0 = 0x7fffffff, j1 = j0, j2 = j0, j3 = j0;
        for (int q = 0; q < 512; q++) {
            float v = sv[q]; int s = si[q];
            bool c3 = (v > w3) || (v == w3 && s < j3);
            if (c3) {
                bool c0 = (v > w0) || (v == w0 && s < j0);
                bool c1 = (v > w1) || (v == w1 && s < j1);
                bool c2 = (v > w2) || (v == w2 && s < j2);
                if (c0)      { w3 = w2; j3 = j2; w2 = w1; j2 = j1; w1 = w0; j1 = j0; w0 = v; j0 = s; }
                else if (c1) { w3 = w2; j3 = j2; w2 = w1; j2 = j1; w1 = v; j1 = s; }
                else if (c2) { w3 = w2; j3 = j2; w2 = v; j2 = s; }
                else         { w3 = v; j3 = s; }
            }
        }
        float e0 = 1.f, e1 = expf(w1 - w0), e2 = expf(w2 - w0), e3 = expf(w3 - w0);
        float inv = 1.f / (e0 + e1 + e2 + e3);
        sp[0] = e0 * inv; sp[1] = e1 * inv; sp[2] = e2 * inv; sp[3] = e3 * inv;
        sx[0] = j0; sx[1] = j1; sx[2] = j2; sx[3] = j3;
    }
    __syncthreads();
    const float* ss = arr_state(srcW, b);
    const float* svp = arr_val(srcW, b);
    float p0 = sp[0], p1 = sp[1], p2 = sp[2], p3 = sp[3];
    int a0 = sx[0], a1 = sx[1], a2 = sx[2], a3 = sx[3];
    float4 os = {0, 0, 0, 0}, ov = {0, 0, 0, 0};
    float4 x, y;
    x = ((const float4*)(ss + (long long)a0 * DIMS))[t]; y = ((const float4*)(svp + (long long)a0 * DIMS))[t];
    os.x += p0 * x.x; os.y += p0 * x.y; os.z += p0 * x.z; os.w += p0 * x.w;
    ov.x += p0 * y.x; ov.y += p0 * y.y; ov.z += p0 * y.z; ov.w += p0 * y.w;
    x = ((const float4*)(ss + (long long)a1 * DIMS))[t]; y = ((const float4*)(svp + (long long)a1 * DIMS))[t];
    os.x += p1 * x.x; os.y += p1 * x.y; os.z += p1 * x.z; os.w += p1 * x.w;
    ov.x += p1 * y.x; ov.y += p1 * y.y; ov.z += p1 * y.z; ov.w += p1 * y.w;
    x = ((const float4*)(ss + (long long)a2 * DIMS))[t]; y = ((const float4*)(svp + (long long)a2 * DIMS))[t];
    os.x += p2 * x.x; os.y += p2 * x.y; os.z += p2 * x.z; os.w += p2 * x.w;
    ov.x += p2 * y.x; ov.y += p2 * y.y; ov.z += p2 * y.z; ov.w += p2 * y.w;
    x = ((const float4*)(ss + (long long)a3 * DIMS))[t]; y = ((const float4*)(svp + (long long)a3 * DIMS))[t];
    os.x += p3 * x.x; os.y += p3 * x.y; os.z += p3 * x.z; os.w += p3 * x.w;
    ov.x += p3 * y.x; ov.y += p3 * y.y; ov.z += p3 * y.z; ov.w += p3 * y.w;
    float4* ts = (float4*)g_tmp_state[b][n];
    float4* tv = (float4*)g_tmp_val[b][n];
    if (acc) {   // accumulate prior tmp contents (e2s result) before use
        float4 u = ts[t]; os.x += u.x; os.y += u.y; os.z += u.z; os.w += u.w;
        float4 v = tv[t]; ov.x += v.x; ov.y += v.y; ov.z += v.z; ov.w += v.w;
    }
    if (doApply) {
        float4* st = (float4*)(arr_state(dstW, b) + (long long)n * DIMS);
        float4* vl = (float4*)(arr_val(dstW, b)   + (long long)n * DIMS);
        float4 a = st[t];
        a.x += coef * os.x; a.y += coef * os.y; a.z += coef * os.z; a.w += coef * os.w;
        st[t] = a;
        float4 c4 = vl[t];
        c4.x += coef * ov.x; c4.y += coef * ov.y; c4.z += coef * ov.z; c4.w += coef * ov.w;
        vl[t] = c4;
    } else {
        ts[t] = os;
        tv[t] = ov;
    }
}

// ---------------- stabilize: state=tanh(state); val=LayerNorm(val) ----------------
__device__ __forceinline__ float blk_sum(float v, float* sm, int t) {
#pragma unroll
    for (int o = 16; o; o >>= 1) v += __shfl_xor_sync(0xffffffffu, v, o);
    if ((t & 31) == 0) sm[t >> 5] = v;
    __syncthreads();
    v = sm[0] + sm[1] + sm[2] + sm[3];
    __syncthreads();
    return v;
}

__global__ void k_stabilize(int which, const float* __restrict__ g, const float* __restrict__ be) {
    __shared__ float sm[4];
    int b = blockIdx.y, n = blockIdx.x, t = threadIdx.x;
    float* st = arr_state(which, b) + (long long)n * DIMS;
    float* vl = arr_val(which, b) + (long long)n * DIMS;
    float4 s4 = ((float4*)st)[t];
    s4.x = tanhf(s4.x); s4.y = tanhf(s4.y); s4.z = tanhf(s4.z); s4.w = tanhf(s4.w);
    ((float4*)st)[t] = s4;
    float4 v4 = ((float4*)vl)[t];
    float sum = v4.x + v4.y + v4.z + v4.w;
    sum = blk_sum(sum, sm, t);
    float mean = sum * (1.f / DIMS);
    float dx = v4.x - mean, dy = v4.y - mean, dz = v4.z - mean, dw = v4.w - mean;
    float sq = dx * dx + dy * dy + dz * dz + dw * dw;
    sq = blk_sum(sq, sm, t);
    float inv = rsqrtf(sq * (1.f / DIMS) + 1e-5f);
    float4 g4 = ((const float4*)g)[t], b4 = ((const float4*)be)[t];
    v4.x = dx * inv * g4.x + b4.x;
    v4.y = dy * inv * g4.y + b4.y;
    v4.z = dz * inv * g4.z + b4.z;
    v4.w = dw * inv * g4.w + b4.w;
    ((float4*)vl)[t] = v4;
}

// ---------------- host orchestration ----------------
extern "C" void kernel_launch(void* const* d_in, const int* in_sizes, int n_in,
                              void* d_out, int out_size) {
    (void)out_size;
    const int*   tokens    = (const int*)d_in[0];
    const float* embed     = (const float*)d_in[1];
    const float* readout_w = (const float*)d_in[2];
    const float* readout_b = (const float*)d_in[3];
    const float* w_s   = (const float*)d_in[4];
    const float* w_se  = (const float*)d_in[5];
    const float* w_sc  = (const float*)d_in[6];
    const float* w_s2e = (const float*)d_in[7];
    const float* w_e2s = (const float*)d_in[8];
    const float* w_s2c = (const float*)d_in[9];
    const float* w_c2s = (const float*)d_in[10];
    const float* ln_s_g = (const float*)d_in[11];
    const float* ln_s_b = (const float*)d_in[12];
    const float* ln_e_g = (const float*)d_in[13];
    const float* ln_e_b = (const float*)d_in[14];
    const float* ln_c_g = (const float*)d_in[15];
    const float* ln_c_b = (const float*)d_in[16];

    static const int NE[3] = {2151, 2253, 2458};
    static const int NC[3] = {1844, 1639, 1434};
    const float* pe_e[3] = {0, 0, 0};
    const float* pe_c[3] = {0, 0, 0};
    for (int i = 17; i < n_in; i++) {
        long long sz = in_sizes[i];
        for (int st = 0; st < 3; st++) {
            if (sz == (long long)NE[st] * DIMS) pe_e[st] = (const float*)d_in[i];
            if (sz == (long long)NC[st] * DIMS) pe_c[st] = (const float*)d_in[i];
        }
    }

    const float AL[3][3] = {{0.3f, 0.25f, 0.15f}, {0.65f, 0.55f, 0.35f}, {1.0f, 0.9f, 0.8f}};
    const int STL[3] = {2, 2, 1};

    auto applyK = [&](int which, int N, float coef) {
        long long tot = (long long)N * (DIMS / 4);
        int blocks = (int)((tot + 255) / 256);
        k_apply<<<dim3(blocks, NBATCH), 256>>>(which, N, coef);
    };
    // doApply=1 only when dst arrays != src arrays (no cross-block race)
    auto attend = [&](int dstW, int srcW, int M, int N, const float* w, int acc, int doSrc,
                      int doApply, float coef) {
        k_split_dst<<<dim3(M, NBATCH), 128>>>(dstW, w);
        if (doSrc) k_split_src<<<dim3(N, NBATCH), 128>>>(srcW);
        k_mma_gemm<<<dim3((N + 127) / 128, (M + 127) / 128, NBATCH), 256>>>(
            M, N, SLD, (long long)EMAX * K2, (long long)EMAX * K2, (long long)EMAX * SLD,
            0, nullptr, nullptr);
        k_topk_gather<<<dim3(M, NBATCH), 128>>>(N, srcW, acc, dstW, coef, doApply);
    };

    k_embed_init<<<dim3(SEQL, NBATCH), 128>>>(tokens, embed);

    int li = 0;
    for (int st = 0; st < 3; st++) {
        int ne = NE[st], nc = NC[st];
        float alpha = AL[st][0], bs2b = AL[st][1], bb2s = AL[st][2];
        k_bcast<<<dim3(ne, NBATCH), 128>>>(pe_e[st], 1);
        k_bcast<<<dim3(nc, NBATCH), 128>>>(pe_c[st], 2);
        for (int l = 0; l < STL[st]; l++) {
            float cx = 0.15f * bs2b * alpha;     // S->B coef
            float cb = 0.2f * alpha;             // B self coef
            float cs = 0.15f * bb2s;             // B->S coef
            k_winprop<<<dim3(SEQL, NBATCH), 128>>>(w_s + li * DIMS);
            applyK(0, SEQL, 0.25f);
            // S->E / S->C: dst(e/c) != src(s) -> fused apply
            attend(1, 0, ne, SEQL, w_s2e + li * DIMS, 0, 1, 1, cx);
            attend(2, 0, nc, SEQL, w_s2c + li * DIMS, 0, 0, 1, cx);
            // B self: dst == src -> unfused (race-free via tmp), then apply
            attend(1, 1, ne, ne, w_se + li * DIMS, 0, 1, 0, 0.f); applyK(1, ne, cb);
            attend(2, 2, nc, nc, w_sc + li * DIMS, 0, 1, 0, 0.f); applyK(2, nc, cb);
            // B->S: e2s to tmp; c2s accumulates tmp and applies to S (dst != src)
            attend(0, 1, SEQL, ne, w_e2s + li * DIMS, 0, 1, 0, 0.f);
            attend(0, 2, SEQL, nc, w_c2s + li * DIMS, 1, 1, 1, cs);
            k_stabilize<<<dim3(SEQL, NBATCH), 128>>>(0, ln_s_g + li * DIMS, ln_s_b + li * DIMS);
            k_stabilize<<<dim3(ne, NBATCH), 128>>>(1, ln_e_g + li * DIMS, ln_e_b + li * DIMS);
            k_stabilize<<<dim3(nc, NBATCH), 128>>>(2, ln_c_g + li * DIMS, ln_c_b + li * DIMS);
            li++;
        }
    }

    // readout: split conversions + tensor-core GEMM
    k_split_a_flat<<<NBATCH * SEQL, 128>>>();
    k_split_w<<<dim3(NV / 32, DIMS / 32), dim3(32, 8)>>>(readout_w);
    k_mma_gemm<<<dim3(NV / 128, (NBATCH * SEQL) / 128, 1), 256>>>(
        NBATCH * SEQL, NV, NV, 0, 0, 0, 1, (float*)d_out, readout_b);
}